// round 1
// baseline (speedup 1.0000x reference)
#include <cuda_runtime.h>

// SpatialTransformer: 3D trilinear grid_sample with border padding,
// align_corners=True (identity grid + flow in voxel units).
// Shapes fixed by the problem: B=2, C=1, D=160, H=192, W=224.

#define DD 160
#define HH 192
#define WW 224
#define PLANE (DD * HH * WW)   // 6,881,280
#define BB 2

__device__ __forceinline__ float clampf(float x, float lo, float hi) {
    return fminf(fmaxf(x, lo), hi);
}

// Sample one output voxel at (d,h,w) with displacement (fd_, fh_, fw_).
__device__ __forceinline__ float sample_one(
    const float* __restrict__ sb,  // src base for this batch [D,H,W]
    int d, int h, int w,
    float dd, float dh, float dw)
{
    float cd = clampf((float)d + dd, 0.0f, (float)(DD - 1));
    float ch = clampf((float)h + dh, 0.0f, (float)(HH - 1));
    float cw = clampf((float)w + dw, 0.0f, (float)(WW - 1));

    int d0 = __float2int_rd(cd);
    int h0 = __float2int_rd(ch);
    int w0 = __float2int_rd(cw);
    int d1 = min(d0 + 1, DD - 1);
    int h1 = min(h0 + 1, HH - 1);
    int w1 = min(w0 + 1, WW - 1);

    float fd = cd - (float)d0;
    float fh = ch - (float)h0;
    float fw = cw - (float)w0;

    long base00 = (long)d0 * (HH * WW) + (long)h0 * WW;
    long base01 = (long)d0 * (HH * WW) + (long)h1 * WW;
    long base10 = (long)d1 * (HH * WW) + (long)h0 * WW;
    long base11 = (long)d1 * (HH * WW) + (long)h1 * WW;

    float c000 = __ldg(sb + base00 + w0);
    float c001 = __ldg(sb + base00 + w1);
    float c010 = __ldg(sb + base01 + w0);
    float c011 = __ldg(sb + base01 + w1);
    float c100 = __ldg(sb + base10 + w0);
    float c101 = __ldg(sb + base10 + w1);
    float c110 = __ldg(sb + base11 + w0);
    float c111 = __ldg(sb + base11 + w1);

    // interpolate along w, then h, then d
    float x00 = c000 + fw * (c001 - c000);
    float x01 = c010 + fw * (c011 - c010);
    float x10 = c100 + fw * (c101 - c100);
    float x11 = c110 + fw * (c111 - c110);
    float y0  = x00 + fh * (x01 - x00);
    float y1  = x10 + fh * (x11 - x10);
    return y0 + fd * (y1 - y0);
}

__global__ void __launch_bounds__(256)
spatial_transformer_kernel(const float* __restrict__ src,
                           const float* __restrict__ flow,
                           float* __restrict__ out)
{
    // Each thread handles 4 consecutive w-voxels (W=224 divisible by 4).
    const int total4 = BB * PLANE / 4;
    int t = blockIdx.x * blockDim.x + threadIdx.x;
    if (t >= total4) return;

    long i = (long)t * 4;           // linear index into [B, D, H, W]
    int b  = (int)(i / PLANE);
    long r = i - (long)b * PLANE;   // index within the [D,H,W] volume
    int d  = (int)(r / (HH * WW));
    int hw = (int)(r - (long)d * (HH * WW));
    int h  = hw / WW;
    int w  = hw - h * WW;

    const float* fb = flow + (long)b * 3 * PLANE;
    float4 fd4 = *reinterpret_cast<const float4*>(fb + r);                 // channel 0: d-disp
    float4 fh4 = *reinterpret_cast<const float4*>(fb + PLANE + r);        // channel 1: h-disp
    float4 fw4 = *reinterpret_cast<const float4*>(fb + 2L * PLANE + r);   // channel 2: w-disp

    const float* sb = src + (long)b * PLANE;

    float4 o;
    o.x = sample_one(sb, d, h, w + 0, fd4.x, fh4.x, fw4.x);
    o.y = sample_one(sb, d, h, w + 1, fd4.y, fh4.y, fw4.y);
    o.z = sample_one(sb, d, h, w + 2, fd4.z, fh4.z, fw4.z);
    o.w = sample_one(sb, d, h, w + 3, fd4.w, fh4.w, fw4.w);

    *reinterpret_cast<float4*>(out + i) = o;
}

extern "C" void kernel_launch(void* const* d_in, const int* in_sizes, int n_in,
                              void* d_out, int out_size)
{
    const float* src  = (const float*)d_in[0];
    const float* flow = (const float*)d_in[1];
    float* out = (float*)d_out;

    const int total4 = BB * PLANE / 4;  // 3,440,640 threads
    const int threads = 256;
    const int blocks = (total4 + threads - 1) / threads;
    spatial_transformer_kernel<<<blocks, threads>>>(src, flow, out);
}

// round 2
// speedup vs baseline: 1.0615x; 1.0615x over previous
#include <cuda_runtime.h>

// SpatialTransformer: 3D trilinear grid_sample, border padding, align_corners.
// Shapes fixed: B=2, C=1, D=160, H=192, W=224.
//
// Round-2 optimization: L1-wavefront reduction. The two w-taps of each
// (d,h) corner row are adjacent floats; fetch the aligned float4 quad
// containing w0 in ONE load (both taps inside it with prob 3/4), with a
// predicated scalar fix-up load when the pair straddles the quad boundary.
// Gather instructions per voxel: 8 -> ~4.25, halving L1tex wavefronts.

#define DD 160
#define HH 192
#define WW 224
#define PLANE (DD * HH * WW)   // 6,881,280
#define BB 2

__device__ __forceinline__ float clampf(float x, float lo, float hi) {
    return fminf(fmaxf(x, lo), hi);
}

// Branchless dynamic extract from a register float4 (o in [0,3]).
__device__ __forceinline__ float sel4(float4 f, int o) {
    float ab = (o & 1) ? f.y : f.x;
    float cd = (o & 1) ? f.w : f.z;
    return (o & 2) ? cd : ab;
}

// Interpolate along w for one (d,h) corner row.
// Loads the aligned float4 quad containing w0; fix-up scalar load if
// w1 falls one past the quad (o1 == 4; then a+4 == w1 <= W-1, in bounds).
__device__ __forceinline__ float row_lerp_w(
    const float* __restrict__ rowbase, int w0, int w1, float fw)
{
    int a  = w0 & ~3;
    int o0 = w0 & 3;
    int o1 = w1 - a;           // in {o0, o0+1} subset of [0,4]
    float4 f = *reinterpret_cast<const float4*>(rowbase + a);
    float lo = sel4(f, o0);
    float hi = sel4(f, o1 & 3);
    if (o1 == 4) hi = __ldg(rowbase + a + 4);
    return lo + fw * (hi - lo);
}

__device__ __forceinline__ float sample_one(
    const float* __restrict__ sb,  // src base for this batch [D,H,W]
    int d, int h, int w,
    float dd, float dh, float dw)
{
    float cd = clampf((float)d + dd, 0.0f, (float)(DD - 1));
    float ch = clampf((float)h + dh, 0.0f, (float)(HH - 1));
    float cw = clampf((float)w + dw, 0.0f, (float)(WW - 1));

    int d0 = __float2int_rd(cd);
    int h0 = __float2int_rd(ch);
    int w0 = __float2int_rd(cw);
    int d1 = min(d0 + 1, DD - 1);
    int h1 = min(h0 + 1, HH - 1);
    int w1 = min(w0 + 1, WW - 1);

    float fd = cd - (float)d0;
    float fh = ch - (float)h0;
    float fw = cw - (float)w0;

    const float* r00 = sb + (long)d0 * (HH * WW) + (long)h0 * WW;
    const float* r01 = sb + (long)d0 * (HH * WW) + (long)h1 * WW;
    const float* r10 = sb + (long)d1 * (HH * WW) + (long)h0 * WW;
    const float* r11 = sb + (long)d1 * (HH * WW) + (long)h1 * WW;

    float x00 = row_lerp_w(r00, w0, w1, fw);
    float x01 = row_lerp_w(r01, w0, w1, fw);
    float x10 = row_lerp_w(r10, w0, w1, fw);
    float x11 = row_lerp_w(r11, w0, w1, fw);

    float y0 = x00 + fh * (x01 - x00);
    float y1 = x10 + fh * (x11 - x10);
    return y0 + fd * (y1 - y0);
}

__global__ void __launch_bounds__(256)
spatial_transformer_kernel(const float* __restrict__ src,
                           const float* __restrict__ flow,
                           float* __restrict__ out)
{
    const int total4 = BB * PLANE / 4;
    int t = blockIdx.x * blockDim.x + threadIdx.x;
    if (t >= total4) return;

    long i = (long)t * 4;           // linear index into [B, D, H, W]
    int b  = (int)(i / PLANE);
    long r = i - (long)b * PLANE;
    int d  = (int)(r / (HH * WW));
    int hw = (int)(r - (long)d * (HH * WW));
    int h  = hw / WW;
    int w  = hw - h * WW;

    const float* fb = flow + (long)b * 3 * PLANE;
    float4 fd4 = *reinterpret_cast<const float4*>(fb + r);
    float4 fh4 = *reinterpret_cast<const float4*>(fb + PLANE + r);
    float4 fw4 = *reinterpret_cast<const float4*>(fb + 2L * PLANE + r);

    const float* sb = src + (long)b * PLANE;

    float4 o;
    o.x = sample_one(sb, d, h, w + 0, fd4.x, fh4.x, fw4.x);
    o.y = sample_one(sb, d, h, w + 1, fd4.y, fh4.y, fw4.y);
    o.z = sample_one(sb, d, h, w + 2, fd4.z, fh4.z, fw4.z);
    o.w = sample_one(sb, d, h, w + 3, fd4.w, fh4.w, fw4.w);

    *reinterpret_cast<float4*>(out + i) = o;
}

extern "C" void kernel_launch(void* const* d_in, const int* in_sizes, int n_in,
                              void* d_out, int out_size)
{
    const float* src  = (const float*)d_in[0];
    const float* flow = (const float*)d_in[1];
    float* out = (float*)d_out;

    const int total4 = BB * PLANE / 4;
    const int threads = 256;
    const int blocks = (total4 + threads - 1) / threads;
    spatial_transformer_kernel<<<blocks, threads>>>(src, flow, out);
}

// round 4
// speedup vs baseline: 1.2797x; 1.2055x over previous
#include <cuda_runtime.h>

// SpatialTransformer: 3D trilinear grid_sample, border padding, align_corners.
// Shapes fixed: B=2, C=1, D=160, H=192, W=224.
//
// Round-4 (re-run of round-3; infra failure): 3D-tiled blocks for L1 tap
// reuse. Each block covers an (8d x 8h x 16w) output brick (1024 voxels,
// 256 threads x 4 w-voxels). Tap footprint ~194KB fits the 228KB L1,
// capturing cross-voxel reuse of src sectors (cuts L1 fill wavefronts +
// L2 sector traffic ~2x). Flow loads / out stores use .cs streaming hints
// so they don't evict taps.

#define DD 160
#define HH 192
#define WW 224
#define PLANE (DD * HH * WW)   // 6,881,280
#define BB 2

// Tile: 16 w x 8 h x 8 d. Grid: x=224/16=14, y=192/8=24, z=2*160/8=40.
#define TW 16
#define TH 8
#define TD 8

__device__ __forceinline__ float clampf(float x, float lo, float hi) {
    return fminf(fmaxf(x, lo), hi);
}

// Branchless dynamic extract from a register float4 (o in [0,3]).
__device__ __forceinline__ float sel4(float4 f, int o) {
    float ab = (o & 1) ? f.y : f.x;
    float cd = (o & 1) ? f.w : f.z;
    return (o & 2) ? cd : ab;
}

// Interpolate along w for one (d,h) corner row using one aligned float4
// quad load (+ rare scalar fix-up when the pair straddles the quad).
__device__ __forceinline__ float row_lerp_w(
    const float* __restrict__ rowbase, int w0, int w1, float fw)
{
    int a  = w0 & ~3;
    int o0 = w0 & 3;
    int o1 = w1 - a;           // in [0,4]
    float4 f = *reinterpret_cast<const float4*>(rowbase + a);
    float lo = sel4(f, o0);
    float hi = sel4(f, o1 & 3);
    if (o1 == 4) hi = __ldg(rowbase + a + 4);
    return lo + fw * (hi - lo);
}

__device__ __forceinline__ float sample_one(
    const float* __restrict__ sb,  // src base for this batch [D,H,W]
    int d, int h, int w,
    float dd, float dh, float dw)
{
    float cd = clampf((float)d + dd, 0.0f, (float)(DD - 1));
    float ch = clampf((float)h + dh, 0.0f, (float)(HH - 1));
    float cw = clampf((float)w + dw, 0.0f, (float)(WW - 1));

    int d0 = __float2int_rd(cd);
    int h0 = __float2int_rd(ch);
    int w0 = __float2int_rd(cw);
    int d1 = min(d0 + 1, DD - 1);
    int h1 = min(h0 + 1, HH - 1);
    int w1 = min(w0 + 1, WW - 1);

    float fd = cd - (float)d0;
    float fh = ch - (float)h0;
    float fw = cw - (float)w0;

    const float* r00 = sb + (long)d0 * (HH * WW) + (long)h0 * WW;
    const float* r01 = sb + (long)d0 * (HH * WW) + (long)h1 * WW;
    const float* r10 = sb + (long)d1 * (HH * WW) + (long)h0 * WW;
    const float* r11 = sb + (long)d1 * (HH * WW) + (long)h1 * WW;

    float x00 = row_lerp_w(r00, w0, w1, fw);
    float x01 = row_lerp_w(r01, w0, w1, fw);
    float x10 = row_lerp_w(r10, w0, w1, fw);
    float x11 = row_lerp_w(r11, w0, w1, fw);

    float y0 = x00 + fh * (x01 - x00);
    float y1 = x10 + fh * (x11 - x10);
    return y0 + fd * (y1 - y0);
}

__global__ void __launch_bounds__(256)
spatial_transformer_kernel(const float* __restrict__ src,
                           const float* __restrict__ flow,
                           float* __restrict__ out)
{
    // 3D brick decomposition.
    int tid = threadIdx.x;
    int wi = (tid & 3) * 4;        // 0,4,8,12 within tile (4 voxels each)
    int hi = (tid >> 2) & 7;       // 0..7
    int di = tid >> 5;             // 0..7 (one d-slice per warp)

    int zb = blockIdx.z;           // 0..39
    int b  = zb / (DD / TD);       // batch
    int dt = zb - b * (DD / TD);

    int d = dt * TD + di;
    int h = blockIdx.y * TH + hi;
    int w = blockIdx.x * TW + wi;

    long r = (long)d * (HH * WW) + (long)h * WW + w;   // index in [D,H,W]
    long i = (long)b * PLANE + r;                       // index in [B,D,H,W]

    const float* fb = flow + (long)b * 3 * PLANE;
    // Streaming loads: don't pollute L1 (tap working set lives there).
    float4 fd4 = __ldcs(reinterpret_cast<const float4*>(fb + r));
    float4 fh4 = __ldcs(reinterpret_cast<const float4*>(fb + PLANE + r));
    float4 fw4 = __ldcs(reinterpret_cast<const float4*>(fb + 2L * PLANE + r));

    const float* sb = src + (long)b * PLANE;

    float4 o;
    o.x = sample_one(sb, d, h, w + 0, fd4.x, fh4.x, fw4.x);
    o.y = sample_one(sb, d, h, w + 1, fd4.y, fh4.y, fw4.y);
    o.z = sample_one(sb, d, h, w + 2, fd4.z, fh4.z, fw4.z);
    o.w = sample_one(sb, d, h, w + 3, fd4.w, fh4.w, fw4.w);

    __stcs(reinterpret_cast<float4*>(out + i), o);
}

extern "C" void kernel_launch(void* const* d_in, const int* in_sizes, int n_in,
                              void* d_out, int out_size)
{
    const float* src  = (const float*)d_in[0];
    const float* flow = (const float*)d_in[1];
    float* out = (float*)d_out;

    dim3 grid(WW / TW, HH / TH, BB * (DD / TD));  // 14 x 24 x 40
    spatial_transformer_kernel<<<grid, 256>>>(src, flow, out);
}

// round 5
// speedup vs baseline: 1.3179x; 1.0299x over previous
#include <cuda_runtime.h>

// SpatialTransformer: 3D trilinear grid_sample, border padding, align_corners.
// Shapes fixed: B=2, C=1, D=160, H=192, W=224.
//
// Round-5: bigger bricks for L1 fill reduction. 1024-thread blocks cover a
// (16d x 16h x 16w) output brick (4096 voxels, 4 w-voxels/thread). One
// resident block per SM owns the whole 228KB L1; halo amortization cuts
// L2->L1 fill traffic ~2.5x vs the 8x8x16 tiles. Access-wavefront scheme
// unchanged (aligned float4 quad per (d,h) row pair + rare fix-up).

#define DD 160
#define HH 192
#define WW 224
#define PLANE (DD * HH * WW)   // 6,881,280
#define BB 2

// Tile: 16 w x 16 h x 16 d. Grid: x=224/16=14, y=192/16=12, z=2*160/16=20.
#define TW 16
#define TH 16
#define TD 16

__device__ __forceinline__ float clampf(float x, float lo, float hi) {
    return fminf(fmaxf(x, lo), hi);
}

// Branchless dynamic extract from a register float4 (o in [0,3]).
__device__ __forceinline__ float sel4(float4 f, int o) {
    float ab = (o & 1) ? f.y : f.x;
    float cd = (o & 1) ? f.w : f.z;
    return (o & 2) ? cd : ab;
}

// Interpolate along w for one (d,h) corner row using one aligned float4
// quad load (+ rare scalar fix-up when the pair straddles the quad).
__device__ __forceinline__ float row_lerp_w(
    const float* __restrict__ rowbase, int w0, int w1, float fw)
{
    int a  = w0 & ~3;
    int o0 = w0 & 3;
    int o1 = w1 - a;           // in [0,4]
    float4 f = *reinterpret_cast<const float4*>(rowbase + a);
    float lo = sel4(f, o0);
    float hi = sel4(f, o1 & 3);
    if (o1 == 4) hi = __ldg(rowbase + a + 4);
    return lo + fw * (hi - lo);
}

__device__ __forceinline__ float sample_one(
    const float* __restrict__ sb,  // src base for this batch [D,H,W]
    int d, int h, int w,
    float dd, float dh, float dw)
{
    float cd = clampf((float)d + dd, 0.0f, (float)(DD - 1));
    float ch = clampf((float)h + dh, 0.0f, (float)(HH - 1));
    float cw = clampf((float)w + dw, 0.0f, (float)(WW - 1));

    int d0 = __float2int_rd(cd);
    int h0 = __float2int_rd(ch);
    int w0 = __float2int_rd(cw);
    int d1 = min(d0 + 1, DD - 1);
    int h1 = min(h0 + 1, HH - 1);
    int w1 = min(w0 + 1, WW - 1);

    float fd = cd - (float)d0;
    float fh = ch - (float)h0;
    float fw = cw - (float)w0;

    const float* r00 = sb + (long)d0 * (HH * WW) + (long)h0 * WW;
    const float* r01 = sb + (long)d0 * (HH * WW) + (long)h1 * WW;
    const float* r10 = sb + (long)d1 * (HH * WW) + (long)h0 * WW;
    const float* r11 = sb + (long)d1 * (HH * WW) + (long)h1 * WW;

    float x00 = row_lerp_w(r00, w0, w1, fw);
    float x01 = row_lerp_w(r01, w0, w1, fw);
    float x10 = row_lerp_w(r10, w0, w1, fw);
    float x11 = row_lerp_w(r11, w0, w1, fw);

    float y0 = x00 + fh * (x01 - x00);
    float y1 = x10 + fh * (x11 - x10);
    return y0 + fd * (y1 - y0);
}

__global__ void __launch_bounds__(1024)
spatial_transformer_kernel(const float* __restrict__ src,
                           const float* __restrict__ flow,
                           float* __restrict__ out)
{
    // 3D brick decomposition: 1024 threads = 4 w-groups x 16 h x 16 d.
    int tid = threadIdx.x;
    int wi = (tid & 3) * 4;        // 0,4,8,12 within tile (4 voxels each)
    int hi = (tid >> 2) & 15;      // 0..15
    int di = tid >> 6;             // 0..15

    int zb = blockIdx.z;           // 0..19
    int b  = zb / (DD / TD);       // batch
    int dt = zb - b * (DD / TD);

    int d = dt * TD + di;
    int h = blockIdx.y * TH + hi;
    int w = blockIdx.x * TW + wi;

    long r = (long)d * (HH * WW) + (long)h * WW + w;   // index in [D,H,W]
    long i = (long)b * PLANE + r;                       // index in [B,D,H,W]

    const float* fb = flow + (long)b * 3 * PLANE;
    // Streaming loads: don't pollute L1 (tap working set lives there).
    float4 fd4 = __ldcs(reinterpret_cast<const float4*>(fb + r));
    float4 fh4 = __ldcs(reinterpret_cast<const float4*>(fb + PLANE + r));
    float4 fw4 = __ldcs(reinterpret_cast<const float4*>(fb + 2L * PLANE + r));

    const float* sb = src + (long)b * PLANE;

    float4 o;
    o.x = sample_one(sb, d, h, w + 0, fd4.x, fh4.x, fw4.x);
    o.y = sample_one(sb, d, h, w + 1, fd4.y, fh4.y, fw4.y);
    o.z = sample_one(sb, d, h, w + 2, fd4.z, fh4.z, fw4.z);
    o.w = sample_one(sb, d, h, w + 3, fd4.w, fh4.w, fw4.w);

    __stcs(reinterpret_cast<float4*>(out + i), o);
}

extern "C" void kernel_launch(void* const* d_in, const int* in_sizes, int n_in,
                              void* d_out, int out_size)
{
    const float* src  = (const float*)d_in[0];
    const float* flow = (const float*)d_in[1];
    float* out = (float*)d_out;

    dim3 grid(WW / TW, HH / TH, BB * (DD / TD));  // 14 x 12 x 20
    spatial_transformer_kernel<<<grid, 1024>>>(src, flow, out);
}

// round 8
// speedup vs baseline: 1.5892x; 1.2058x over previous
#include <cuda_runtime.h>

// SpatialTransformer: 3D trilinear grid_sample, border padding, align_corners.
// Shapes fixed: B=2, C=1, D=160, H=192, W=224.
//
// Round-8: persistent blocks + w-adjacent tile runs (restructured re-try of
// the twice-infra-failed round-6/7 source; same algorithm).
// Grid = 148 blocks x 1024 threads (1 resident block/SM). Each block walks
// a contiguous run of the 3360 (16d x 16h x 16w) tiles in w-major order:
// consecutive tiles overlap ~72% of their gather footprint, so the warm L1
// serves most of the next tile's halo. Removes ~21 wave transitions and
// tail quantization of the one-block-per-tile launch.

#define DD 160
#define HH 192
#define WW 224
#define PLANE (DD * HH * WW)   // 6,881,280
#define BB 2

#define TW 16
#define TH 16
#define TD 16
#define NTX 14                   // WW/TW
#define NTY 12                   // HH/TH
#define NTZ 20                   // BB*DD/TD
#define NTILES 3360              // NTX*NTY*NTZ
#define NBLOCKS 148

__device__ __forceinline__ float clampf(float x, float lo, float hi) {
    return fminf(fmaxf(x, lo), hi);
}

__device__ __forceinline__ float sel4(float4 f, int o) {
    float ab = (o & 1) ? f.y : f.x;
    float cd = (o & 1) ? f.w : f.z;
    return (o & 2) ? cd : ab;
}

__device__ __forceinline__ float row_lerp_w(
    const float* __restrict__ rowbase, int w0, int w1, float fw)
{
    int a  = w0 & ~3;
    int o0 = w0 & 3;
    int o1 = w1 - a;           // in [0,4]
    float4 f = *reinterpret_cast<const float4*>(rowbase + a);
    float lo = sel4(f, o0);
    float hi = sel4(f, o1 & 3);
    if (o1 == 4) hi = __ldg(rowbase + a + 4);
    return lo + fw * (hi - lo);
}

__device__ __forceinline__ float sample_one(
    const float* __restrict__ sb,
    int d, int h, int w,
    float dd, float dh, float dw)
{
    float cd = clampf((float)d + dd, 0.0f, (float)(DD - 1));
    float ch = clampf((float)h + dh, 0.0f, (float)(HH - 1));
    float cw = clampf((float)w + dw, 0.0f, (float)(WW - 1));

    int d0 = __float2int_rd(cd);
    int h0 = __float2int_rd(ch);
    int w0 = __float2int_rd(cw);
    int d1 = min(d0 + 1, DD - 1);
    int h1 = min(h0 + 1, HH - 1);
    int w1 = min(w0 + 1, WW - 1);

    float fd = cd - (float)d0;
    float fh = ch - (float)h0;
    float fw = cw - (float)w0;

    const float* r00 = sb + d0 * (HH * WW) + h0 * WW;
    const float* r01 = sb + d0 * (HH * WW) + h1 * WW;
    const float* r10 = sb + d1 * (HH * WW) + h0 * WW;
    const float* r11 = sb + d1 * (HH * WW) + h1 * WW;

    float x00 = row_lerp_w(r00, w0, w1, fw);
    float x01 = row_lerp_w(r01, w0, w1, fw);
    float x10 = row_lerp_w(r10, w0, w1, fw);
    float x11 = row_lerp_w(r11, w0, w1, fw);

    float y0 = x00 + fh * (x01 - x00);
    float y1 = x10 + fh * (x11 - x10);
    return y0 + fd * (y1 - y0);
}

__global__ void __launch_bounds__(1024, 1)
spatial_transformer_kernel(const float* __restrict__ src,
                           const float* __restrict__ flow,
                           float* __restrict__ out)
{
    const int tid = threadIdx.x;
    const int wi = (tid & 3) * 4;        // 0,4,8,12 within tile
    const int hi = (tid >> 2) & 15;      // 0..15
    const int di = tid >> 6;             // 0..15

    // Balanced contiguous chunk: first (NTILES % NBLOCKS) blocks get one extra.
    const int base  = NTILES / NBLOCKS;           // 22
    const int extra = NTILES - base * NBLOCKS;    // 104
    const int bx = blockIdx.x;
    int t0, cnt;
    if (bx < extra) { cnt = base + 1; t0 = bx * cnt; }
    else            { cnt = base;     t0 = extra * (base + 1) + (bx - extra) * base; }

    for (int k = 0; k < cnt; ++k) {
        const int t = t0 + k;
        const int xb = t % NTX;
        const int r2 = t / NTX;
        const int yb = r2 % NTY;
        const int zb = r2 / NTY;             // 0..19
        const int b  = zb / (DD / TD);       // batch
        const int dt = zb - b * (DD / TD);

        const int d = dt * TD + di;
        const int h = yb * TH + hi;
        const int w = xb * TW + wi;

        const int r = d * (HH * WW) + h * WW + w;   // index in [D,H,W]
        const long i = (long)b * PLANE + r;

        const float* fb = flow + (long)b * 3 * PLANE;
        float4 fd4 = __ldcs(reinterpret_cast<const float4*>(fb + r));
        float4 fh4 = __ldcs(reinterpret_cast<const float4*>(fb + PLANE + r));
        float4 fw4 = __ldcs(reinterpret_cast<const float4*>(fb + 2L * PLANE + r));

        const float* sb = src + (long)b * PLANE;

        float4 o;
        o.x = sample_one(sb, d, h, w + 0, fd4.x, fh4.x, fw4.x);
        o.y = sample_one(sb, d, h, w + 1, fd4.y, fh4.y, fw4.y);
        o.z = sample_one(sb, d, h, w + 2, fd4.z, fh4.z, fw4.z);
        o.w = sample_one(sb, d, h, w + 3, fd4.w, fh4.w, fw4.w);

        __stcs(reinterpret_cast<float4*>(out + i), o);
    }
}

extern "C" void kernel_launch(void* const* d_in, const int* in_sizes, int n_in,
                              void* d_out, int out_size)
{
    const float* src  = (const float*)d_in[0];
    const float* flow = (const float*)d_in[1];
    float* out = (float*)d_out;

    spatial_transformer_kernel<<<NBLOCKS, 1024>>>(src, flow, out);
}